// round 11
// baseline (speedup 1.0000x reference)
#include <cuda_runtime.h>
#include <cuda_bf16.h>
#include <math.h>
#include <stdint.h>

#define B_  8
#define T_  2048
#define C_  2048
#define HS_ 64
#define H_  32
#define M_  (B_*T_)   // 16384

// ---------------------------------------------------------------------------
// Static scratch
// ---------------------------------------------------------------------------
#define ACT_E   ((size_t)M_ * C_)          // 33,554,432 elems
#define ACT_BB  (ACT_E * 2)                // 64 MiB per bf16 act buffer
#define W_E     ((size_t)C_ * C_)
#define W_BB    (W_E * 2)                  // 8 MiB per bf16 weight buffer
#define F32_B   (ACT_E * 4)                // 128 MiB per fp32 buffer

__device__ __align__(256) unsigned char g_scratch[8 * ACT_BB + 10 * W_BB + 4 * F32_B];

// ---------------------------------------------------------------------------
// PTX helpers (plain sm_80/sm_90 PTX — valid under compute_103)
// ---------------------------------------------------------------------------
__device__ __forceinline__ uint32_t smem_u32(const void* p) {
    uint32_t a;
    asm("{ .reg .u64 t; cvta.to.shared.u64 t, %1; cvt.u32.u64 %0, t; }" : "=r"(a) : "l"(p));
    return a;
}

__device__ __forceinline__ void cp16(uint32_t so, const void* gp) {
    asm volatile("cp.async.cg.shared.global [%0], [%1], 16;" :: "r"(so), "l"(gp));
}
#define CP_COMMIT() asm volatile("cp.async.commit_group;" ::: "memory")
#define CP_WAIT3()  asm volatile("cp.async.wait_group 3;" ::: "memory")
#define CP_WAIT2()  asm volatile("cp.async.wait_group 2;" ::: "memory")
#define CP_WAIT1()  asm volatile("cp.async.wait_group 1;" ::: "memory")
#define CP_WAIT0()  asm volatile("cp.async.wait_group 0;" ::: "memory")

// named barriers, 384 participants (256 consumers sync / 128 producers arrive etc.)
#define BAR_SYNC(id)   asm volatile("bar.sync %0, 384;"   :: "r"(id) : "memory")
#define BAR_ARRIVE(id) asm volatile("bar.arrive %0, 384;" :: "r"(id) : "memory")

__device__ __forceinline__ void ldsm4(uint32_t& r0, uint32_t& r1, uint32_t& r2, uint32_t& r3,
                                      uint32_t addr) {
    asm volatile("ldmatrix.sync.aligned.m8n8.x4.shared.b16 {%0,%1,%2,%3}, [%4];"
                 : "=r"(r0), "=r"(r1), "=r"(r2), "=r"(r3) : "r"(addr));
}

__device__ __forceinline__ void mma16816(float* c, const uint32_t* a, const uint32_t* b) {
    asm("mma.sync.aligned.m16n8k16.row.col.f32.bf16.bf16.f32 "
        "{%0,%1,%2,%3}, {%4,%5,%6,%7}, {%8,%9}, {%0,%1,%2,%3};"
        : "+f"(c[0]), "+f"(c[1]), "+f"(c[2]), "+f"(c[3])
        : "r"(a[0]), "r"(a[1]), "r"(a[2]), "r"(a[3]), "r"(b[0]), "r"(b[1]));
}

// ---------------------------------------------------------------------------
// Fused weight transpose + split (all 5 weights, blockIdx.z selects).
// ---------------------------------------------------------------------------
__global__ __launch_bounds__(256) void wsplit_all_kernel(
    const float* __restrict__ W0, const float* __restrict__ W1,
    const float* __restrict__ W2, const float* __restrict__ W3,
    const float* __restrict__ W4,
    __nv_bfloat16* __restrict__ wtbase)
{
    __shared__ float tile[32][33];
    const float* Ws[5] = {W0, W1, W2, W3, W4};
    const float* W = Ws[blockIdx.z];
    __nv_bfloat16* hi = wtbase + (size_t)(2 * blockIdx.z)     * W_E;
    __nv_bfloat16* lo = wtbase + (size_t)(2 * blockIdx.z + 1) * W_E;

    int tx = threadIdx.x, ty = threadIdx.y;
    int n0 = blockIdx.x * 32, k0 = blockIdx.y * 32;
#pragma unroll
    for (int r = ty; r < 32; r += 8)
        tile[r][tx] = W[(size_t)(k0 + r) * C_ + n0 + tx];
    __syncthreads();
#pragma unroll
    for (int r = ty; r < 32; r += 8) {
        float v = tile[tx][r];                 // = W[k0+tx][n0+r]
        __nv_bfloat16 h = __float2bfloat16(v);
        size_t o = (size_t)(n0 + r) * C_ + k0 + tx;
        hi[o] = h;
        lo[o] = __float2bfloat16(v - __bfloat162float(h));
    }
}

// ---------------------------------------------------------------------------
// Token-shift mixing fused with fp32 -> (bf16 hi, bf16 lo) split.
// ---------------------------------------------------------------------------
__device__ __forceinline__ void split_store4(__nv_bfloat16* hi, __nv_bfloat16* lo,
                                             size_t idx, float4 o) {
    __nv_bfloat16 h0 = __float2bfloat16(o.x);
    __nv_bfloat16 h1 = __float2bfloat16(o.y);
    __nv_bfloat16 h2 = __float2bfloat16(o.z);
    __nv_bfloat16 h3 = __float2bfloat16(o.w);
    __nv_bfloat162* hp = (__nv_bfloat162*)(hi + idx);
    hp[0] = __nv_bfloat162(h0, h1);
    hp[1] = __nv_bfloat162(h2, h3);
    __nv_bfloat162* lp = (__nv_bfloat162*)(lo + idx);
    lp[0] = __nv_bfloat162(__float2bfloat16(o.x - __bfloat162float(h0)),
                           __float2bfloat16(o.y - __bfloat162float(h1)));
    lp[1] = __nv_bfloat162(__float2bfloat16(o.z - __bfloat162float(h2)),
                           __float2bfloat16(o.w - __bfloat162float(h3)));
}

__global__ __launch_bounds__(256) void mix_split_kernel(
    const float* __restrict__ x,
    const float* __restrict__ tmk, const float* __restrict__ tmv,
    const float* __restrict__ tmr, const float* __restrict__ tmg,
    __nv_bfloat16* __restrict__ xkh, __nv_bfloat16* __restrict__ xkl,
    __nv_bfloat16* __restrict__ xvh, __nv_bfloat16* __restrict__ xvl,
    __nv_bfloat16* __restrict__ xrh, __nv_bfloat16* __restrict__ xrl,
    __nv_bfloat16* __restrict__ xgh, __nv_bfloat16* __restrict__ xgl)
{
    size_t idx4 = (size_t)blockIdx.x * blockDim.x + threadIdx.x;
    size_t idx  = idx4 * 4;
    int    c    = (int)(idx % C_);
    size_t m    = idx / C_;
    int    t    = (int)(m % T_);

    float4 xc = *(const float4*)(x + idx);
    float4 xp = make_float4(0.f, 0.f, 0.f, 0.f);
    if (t != 0) xp = *(const float4*)(x + idx - C_);

    float4 o;
#define DO_MIX(TM, HI, LO)                                                  \
    {                                                                       \
        float4 w4 = *(const float4*)((TM) + c);                             \
        o.x = fmaf(w4.x, xc.x - xp.x, xp.x);                                \
        o.y = fmaf(w4.y, xc.y - xp.y, xp.y);                                \
        o.z = fmaf(w4.z, xc.z - xp.z, xp.z);                                \
        o.w = fmaf(w4.w, xc.w - xp.w, xp.w);                                \
        split_store4(HI, LO, idx, o);                                       \
    }
    DO_MIX(tmk, xkh, xkl)
    DO_MIX(tmv, xvh, xvl)
    DO_MIX(tmr, xrh, xrl)
    DO_MIX(tmg, xgh, xgl)
#undef DO_MIX
}

// ---------------------------------------------------------------------------
// bf16x3 GEMM, warp-specialized: 384 threads.
//   warps 0-7  : consumers (64x32 warp tiles, ldsm + mma only)
//   warps 8-11 : producers (all cp.async)
// 4-stage ring, named barriers FULL[s]=1+s, FREE[s]=5+s (384 participants).
// No __syncthreads in the mainloop.
// ---------------------------------------------------------------------------
#define BM 128
#define BN 128
#define BK 32
#define NCHUNK (2048 / BK)          // 64
#define ROWB 80u                    // bytes per padded smem row (32 bf16 -> 80B)
#define MAT_BYTES (128u * ROWB)     // 10240
#define STAGE_BYTES (4u * MAT_BYTES)  // 40960: Ah, Al, Bh, Bl
#define NSTAGE 4
#define GEMM_SMEM (NSTAGE * STAGE_BYTES)   // 163840
#define OFF_AH 0u
#define OFF_AL (1u * MAT_BYTES)
#define OFF_BH (2u * MAT_BYTES)
#define OFF_BL (3u * MAT_BYTES)

// producer fill: 128 loader threads, 16 cp16 each = 2048 lines
__device__ __forceinline__ void load_stage128(
    uint32_t sstage, int k0, int ltid, int m0, int n0,
    const __nv_bfloat16* Ah, const __nv_bfloat16* Al,
    const __nv_bfloat16* Bh, const __nv_bfloat16* Bl)
{
#pragma unroll
    for (int j = 0; j < 16; j++) {
        int id  = ltid + 128 * j;       // 0..2047
        int sel = id >> 9;              // 0=Ah 1=Al 2=Bh 3=Bl
        int cc  = id & 511;
        int row = cc >> 2, ch = cc & 3;
        const __nv_bfloat16* base = (sel == 0) ? Ah : (sel == 1) ? Al : (sel == 2) ? Bh : Bl;
        int grow = ((sel < 2) ? m0 : n0) + row;
        const void* gp = base + (size_t)grow * 2048 + k0 + ch * 8;
        uint32_t so = sstage + (uint32_t)sel * MAT_BYTES + (uint32_t)row * ROWB + (uint32_t)ch * 16u;
        cp16(so, gp);
    }
    CP_COMMIT();
}

__device__ __forceinline__ void load_frags(
    uint32_t st, int ks, int wm, int wn,
    int a_r, int a_kb, int b_r, int b_kb,
    uint32_t (&ah)[4][4], uint32_t (&al)[4][4],
    uint32_t (&bh)[4][2], uint32_t (&bl)[4][2])
{
#pragma unroll
    for (int mi = 0; mi < 4; mi++) {
        uint32_t arow = (uint32_t)(wm * 64 + mi * 16 + a_r);
        uint32_t ao = arow * ROWB + (uint32_t)(ks * 32 + a_kb);
        ldsm4(ah[mi][0], ah[mi][1], ah[mi][2], ah[mi][3], st + OFF_AH + ao);
        ldsm4(al[mi][0], al[mi][1], al[mi][2], al[mi][3], st + OFF_AL + ao);
    }
#pragma unroll
    for (int bi = 0; bi < 2; bi++) {
        uint32_t brow = (uint32_t)(wn * 32 + bi * 16 + b_r);
        uint32_t bo = brow * ROWB + (uint32_t)(ks * 32 + b_kb);
        uint32_t t0, t1, t2, t3;
        ldsm4(t0, t1, t2, t3, st + OFF_BH + bo);
        bh[bi * 2][0] = t0; bh[bi * 2][1] = t1;
        bh[bi * 2 + 1][0] = t2; bh[bi * 2 + 1][1] = t3;
        ldsm4(t0, t1, t2, t3, st + OFF_BL + bo);
        bl[bi * 2][0] = t0; bl[bi * 2][1] = t1;
        bl[bi * 2 + 1][0] = t2; bl[bi * 2 + 1][1] = t3;
    }
}

__global__ __launch_bounds__(384, 1) void gemm_bf16x3(
    const __nv_bfloat16* __restrict__ Ah, const __nv_bfloat16* __restrict__ Al,
    const __nv_bfloat16* __restrict__ Bh, const __nv_bfloat16* __restrict__ Bl,
    float* __restrict__ Cm, int epi)
{
    extern __shared__ __align__(128) unsigned char dsm[];
    const uint32_t sb = smem_u32(dsm);

    const int tid  = threadIdx.x;
    const int wid  = tid >> 5;
    const int lane = tid & 31;
    const int m0   = blockIdx.y * BM;
    const int n0   = blockIdx.x * BN;

    if (wid >= 8) {
        // ---------------- producer warps ----------------
        const int ltid = tid - 256;     // 0..127
        for (int i = 0; i < NCHUNK; i++) {
            const int s = i & 3;
            if (i >= NSTAGE) BAR_SYNC(5 + s);                    // wait FREE[s]
            load_stage128(sb + (uint32_t)s * STAGE_BYTES, i * BK, ltid,
                          m0, n0, Ah, Al, Bh, Bl);
            if (i >= 3) { CP_WAIT3(); BAR_ARRIVE(1 + ((i - 3) & 3)); }  // FULL
        }
        CP_WAIT2(); BAR_ARRIVE(1 + ((NCHUNK - 3) & 3));
        CP_WAIT1(); BAR_ARRIVE(1 + ((NCHUNK - 2) & 3));
        CP_WAIT0(); BAR_ARRIVE(1 + ((NCHUNK - 1) & 3));
        return;
    }

    // ---------------- consumer warps ----------------
    const int wm = wid >> 2;            // 0..1 -> warp M origin wm*64
    const int wn = wid & 3;             // 0..3 -> warp N origin wn*32

    float acc[4][4][4];
#pragma unroll
    for (int i = 0; i < 4; i++)
#pragma unroll
        for (int j = 0; j < 4; j++)
#pragma unroll
            for (int q = 0; q < 4; q++) acc[i][j][q] = 0.f;

    const int a_r  = (lane & 15);
    const int a_kb = (lane >> 4) * 16;
    const int b_r  = (lane & 7) + ((lane >> 4) * 8);
    const int b_kb = ((lane >> 3) & 1) * 16;

    uint32_t ah[2][4][4], al[2][4][4], bh[2][4][2], bl[2][4][2];

    for (int i = 0; i < NCHUNK; i++) {
        const int s = i & 3;
        const uint32_t st = sb + (uint32_t)s * STAGE_BYTES;
        BAR_SYNC(1 + s);                                          // wait FULL[s]
        load_frags(st, 0, wm, wn, a_r, a_kb, b_r, b_kb, ah[0], al[0], bh[0], bl[0]);
        load_frags(st, 1, wm, wn, a_r, a_kb, b_r, b_kb, ah[1], al[1], bh[1], bl[1]);
        BAR_ARRIVE(5 + s);                                        // FREE[s]
#pragma unroll
        for (int ks = 0; ks < 2; ks++)
#pragma unroll
            for (int mi = 0; mi < 4; mi++)
#pragma unroll
                for (int ng = 0; ng < 4; ng++) {
                    mma16816(acc[mi][ng], ah[ks][mi], bh[ks][ng]);
                    mma16816(acc[mi][ng], ah[ks][mi], bl[ks][ng]);
                    mma16816(acc[mi][ng], al[ks][mi], bh[ks][ng]);
                }
    }

    // epilogue (consumers only)
#pragma unroll
    for (int mi = 0; mi < 4; mi++) {
        int row0 = m0 + wm * 64 + mi * 16 + (lane >> 2);
#pragma unroll
        for (int ng = 0; ng < 4; ng++) {
            int col = n0 + wn * 32 + ng * 8 + (lane & 3) * 2;
            float2 v0 = make_float2(acc[mi][ng][0], acc[mi][ng][1]);
            float2 v1 = make_float2(acc[mi][ng][2], acc[mi][ng][3]);
            if (epi) {
                v0.x = v0.x / (1.f + expf(-v0.x));
                v0.y = v0.y / (1.f + expf(-v0.y));
                v1.x = v1.x / (1.f + expf(-v1.x));
                v1.y = v1.y / (1.f + expf(-v1.y));
            }
            *(float2*)(Cm + (size_t)row0 * 2048 + col)       = v0;
            *(float2*)(Cm + (size_t)(row0 + 8) * 2048 + col) = v1;
        }
    }
}

// ---------------------------------------------------------------------------
// WKV5 recurrence, 2-way split over state rows. 128 threads per (b,h).
// ---------------------------------------------------------------------------
#define CH 16
__global__ __launch_bounds__(128) void wkv_kernel(
    const float* __restrict__ r, const float* __restrict__ k,
    const float* __restrict__ v, const float* __restrict__ decay,
    const float* __restrict__ faaaa, float* __restrict__ y)
{
    const int bh   = blockIdx.x;
    const int b    = bh / H_;
    const int h    = bh % H_;
    const int tid  = threadIdx.x;
    const int j    = tid & 63;
    const int half = tid >> 6;          // 0 or 1
    const int i0   = half * 32;

    __shared__ float rs[CH][HS_], ks_[CH][HS_], vs[CH][HS_];
    __shared__ float part[CH][HS_];
    __shared__ float cpart[2][CH];
    __shared__ float ws[HS_], us[HS_];

    if (half == 0) {
        ws[j] = expf(-expf(decay[h * HS_ + j]));
        us[j] = faaaa[h * HS_ + j];
    }

    float S[32];
#pragma unroll
    for (int i = 0; i < 32; i++) S[i] = 0.f;

    const size_t base = (size_t)b * T_ * C_ + h * HS_;

    for (int t0 = 0; t0 < T_; t0 += CH) {
        __syncthreads();                // smem reuse guard (also covers ws/us init)
#pragma unroll
        for (int ss = 0; ss < 8; ss++) {
            int s = half * 8 + ss;
            size_t off = base + (size_t)(t0 + s) * C_ + j;
            rs[s][j]  = r[off];
            ks_[s][j] = k[off];
            vs[s][j]  = v[off];
        }
        __syncthreads();
        if (j < CH) {                   // per-half partial of c_t
            float c = 0.f;
#pragma unroll
            for (int i = 0; i < 32; i++)
                c = fmaf(rs[j][i0 + i] * us[i0 + i], ks_[j][i0 + i], c);
            cpart[half][j] = c;
        }
        __syncthreads();

        float yy[CH];
        for (int s = 0; s < CH; s++) {
            float vj  = vs[s][j];
            float acc = 0.f;
#pragma unroll
            for (int i = 0; i < 32; i++) {
                acc  = fmaf(rs[s][i0 + i], S[i], acc);   // uses S before update
                S[i] = fmaf(ws[i0 + i], S[i], ks_[s][i0 + i] * vj);
            }
            yy[s] = acc;
        }
        if (half == 1) {
#pragma unroll
            for (int s = 0; s < CH; s++) part[s][j] = yy[s];
        }
        __syncthreads();
        if (half == 0) {
#pragma unroll
            for (int s = 0; s < CH; s++) {
                float c = cpart[0][s] + cpart[1][s];
                y[base + (size_t)(t0 + s) * C_ + j] =
                    yy[s] + part[s][j] + c * vs[s][j];
            }
        }
    }
}
#undef CH

// ---------------------------------------------------------------------------
// GroupNorm (/8, per head) * gate, output split to bf16 hi/lo for Wo GEMM.
// ---------------------------------------------------------------------------
__global__ __launch_bounds__(256) void gnorm_kernel(
    const float* __restrict__ y, const float* __restrict__ g,
    const float* __restrict__ lnw, const float* __restrict__ lnb,
    __nv_bfloat16* __restrict__ zh, __nv_bfloat16* __restrict__ zl)
{
    int warp = blockIdx.x * 8 + (threadIdx.x >> 5);
    int lane = threadIdx.x & 31;
    int row  = warp / H_;
    int h    = warp % H_;

    const size_t o0 = (size_t)row * C_ + h * HS_ + lane;
    float a0 = y[o0]      * 0.125f;
    float a1 = y[o0 + 32] * 0.125f;

    float s = a0 + a1;
#pragma unroll
    for (int o = 16; o; o >>= 1) s += __shfl_xor_sync(0xffffffffu, s, o);
    float mean = s * (1.f / 64.f);

    float d0 = a0 - mean, d1 = a1 - mean;
    float q = d0 * d0 + d1 * d1;
#pragma unroll
    for (int o = 16; o; o >>= 1) q += __shfl_xor_sync(0xffffffffu, q, o);
    float inv = rsqrtf(q * (1.f / 64.f) + 1e-5f);

    int c = h * HS_ + lane;
    float z0 = fmaf(d0 * inv, lnw[c],      lnb[c])      * g[o0];
    float z1 = fmaf(d1 * inv, lnw[c + 32], lnb[c + 32]) * g[o0 + 32];

    __nv_bfloat16 h0 = __float2bfloat16(z0);
    __nv_bfloat16 h1 = __float2bfloat16(z1);
    zh[o0]      = h0;
    zh[o0 + 32] = h1;
    zl[o0]      = __float2bfloat16(z0 - __bfloat162float(h0));
    zl[o0 + 32] = __float2bfloat16(z1 - __bfloat162float(h1));
}

// ---------------------------------------------------------------------------
extern "C" void kernel_launch(void* const* d_in, const int* in_sizes, int n_in,
                              void* d_out, int out_size)
{
    const float* x   = (const float*)d_in[0];
    const float* tmk = (const float*)d_in[1];
    const float* tmv = (const float*)d_in[2];
    const float* tmr = (const float*)d_in[3];
    const float* tmg = (const float*)d_in[4];
    const float* dec = (const float*)d_in[5];
    const float* faa = (const float*)d_in[6];
    const float* Wr  = (const float*)d_in[7];
    const float* Wk  = (const float*)d_in[8];
    const float* Wv  = (const float*)d_in[9];
    const float* Wg  = (const float*)d_in[10];
    const float* Wo  = (const float*)d_in[11];
    const float* lnw = (const float*)d_in[12];
    const float* lnb = (const float*)d_in[13];
    float* out = (float*)d_out;

    unsigned char* sc = nullptr;
    cudaGetSymbolAddress((void**)&sc, g_scratch);

    __nv_bfloat16* act[8];   // xr_hi, xr_lo, xk_hi, xk_lo, xv_hi, xv_lo, xg_hi, xg_lo
    for (int i = 0; i < 8; i++) act[i] = (__nv_bfloat16*)(sc + (size_t)i * ACT_BB);
    __nv_bfloat16* wtbase = (__nv_bfloat16*)(sc + 8 * ACT_BB);
    __nv_bfloat16* wt[10];   // wr, wk, wv, wg, wo (hi/lo pairs)
    for (int i = 0; i < 10; i++) wt[i] = wtbase + (size_t)i * W_E;
    float* f32b = (float*)(sc + 8 * ACT_BB + 10 * W_BB);
    float* rb = f32b + 0 * ACT_E;
    float* kb = f32b + 1 * ACT_E;
    float* vb = f32b + 2 * ACT_E;
    float* gb = f32b + 3 * ACT_E;
    float* yb = (float*)act[2];          // aliases xk hi+lo (dead after k GEMM)
    __nv_bfloat16* zh = act[4];          // aliases xv_hi (dead after v GEMM)
    __nv_bfloat16* zl = act[5];          // aliases xv_lo

    cudaFuncSetAttribute(gemm_bf16x3, cudaFuncAttributeMaxDynamicSharedMemorySize, GEMM_SMEM);

    // launch 1: fused weight split (6th launch overall = gate GEMM gets profiled)
    dim3 wgrid(64, 64, 5);
    dim3 wblk(32, 8);
    wsplit_all_kernel<<<wgrid, wblk>>>(Wr, Wk, Wv, Wg, Wo, wtbase);

    // launch 2: mixing
    mix_split_kernel<<<32768, 256>>>(x, tmk, tmv, tmr, tmg,
                                     act[2], act[3], act[4], act[5],
                                     act[0], act[1], act[6], act[7]);

    // launches 3-6: projection GEMMs
    dim3 ggrid(C_ / BN, M_ / BM);   // (16, 128)
    gemm_bf16x3<<<ggrid, 384, GEMM_SMEM>>>(act[0], act[1], wt[0], wt[1], rb, 0);
    gemm_bf16x3<<<ggrid, 384, GEMM_SMEM>>>(act[2], act[3], wt[2], wt[3], kb, 0);
    gemm_bf16x3<<<ggrid, 384, GEMM_SMEM>>>(act[4], act[5], wt[4], wt[5], vb, 0);
    gemm_bf16x3<<<ggrid, 384, GEMM_SMEM>>>(act[6], act[7], wt[6], wt[7], gb, 1);

    wkv_kernel<<<256, 128>>>(rb, kb, vb, dec, faa, yb);

    gnorm_kernel<<<65536, 256>>>(yb, gb, lnw, lnb, zh, zl);

    gemm_bf16x3<<<ggrid, 384, GEMM_SMEM>>>(zh, zl, wt[8], wt[9], out, 0);
}

// round 12
// speedup vs baseline: 1.2958x; 1.2958x over previous
#include <cuda_runtime.h>
#include <cuda_bf16.h>
#include <math.h>
#include <stdint.h>

#define B_  8
#define T_  2048
#define C_  2048
#define HS_ 64
#define H_  32
#define M_  (B_*T_)   // 16384

// ---------------------------------------------------------------------------
// Static scratch
// ---------------------------------------------------------------------------
#define ACT_E   ((size_t)M_ * C_)          // 33,554,432 elems
#define ACT_BB  (ACT_E * 2)                // 64 MiB per bf16 act buffer
#define W_E     ((size_t)C_ * C_)
#define W_BB    (W_E * 2)                  // 8 MiB per bf16 weight buffer
#define F32_B   (ACT_E * 4)                // 128 MiB per fp32 buffer

__device__ __align__(256) unsigned char g_scratch[8 * ACT_BB + 10 * W_BB + 4 * F32_B];

// ---------------------------------------------------------------------------
// PTX helpers (plain sm_80 PTX — valid under compute_103)
// ---------------------------------------------------------------------------
__device__ __forceinline__ uint32_t smem_u32(const void* p) {
    uint32_t a;
    asm("{ .reg .u64 t; cvta.to.shared.u64 t, %1; cvt.u32.u64 %0, t; }" : "=r"(a) : "l"(p));
    return a;
}

__device__ __forceinline__ void cp16(uint32_t so, const void* gp) {
    asm volatile("cp.async.cg.shared.global [%0], [%1], 16;" :: "r"(so), "l"(gp));
}
#define CP_COMMIT() asm volatile("cp.async.commit_group;" ::: "memory")
#define CP_WAIT2()  asm volatile("cp.async.wait_group 2;" ::: "memory")
#define CP_WAIT0()  asm volatile("cp.async.wait_group 0;" ::: "memory")

__device__ __forceinline__ void ldsm4(uint32_t& r0, uint32_t& r1, uint32_t& r2, uint32_t& r3,
                                      uint32_t addr) {
    asm volatile("ldmatrix.sync.aligned.m8n8.x4.shared.b16 {%0,%1,%2,%3}, [%4];"
                 : "=r"(r0), "=r"(r1), "=r"(r2), "=r"(r3) : "r"(addr));
}

__device__ __forceinline__ void mma16816(float* c, const uint32_t* a, const uint32_t* b) {
    asm("mma.sync.aligned.m16n8k16.row.col.f32.bf16.bf16.f32 "
        "{%0,%1,%2,%3}, {%4,%5,%6,%7}, {%8,%9}, {%0,%1,%2,%3};"
        : "+f"(c[0]), "+f"(c[1]), "+f"(c[2]), "+f"(c[3])
        : "r"(a[0]), "r"(a[1]), "r"(a[2]), "r"(a[3]), "r"(b[0]), "r"(b[1]));
}

// ---------------------------------------------------------------------------
// Fused weight transpose + split (all 5 weights, blockIdx.z selects).
// ---------------------------------------------------------------------------
__global__ __launch_bounds__(256) void wsplit_all_kernel(
    const float* __restrict__ W0, const float* __restrict__ W1,
    const float* __restrict__ W2, const float* __restrict__ W3,
    const float* __restrict__ W4,
    __nv_bfloat16* __restrict__ wtbase)
{
    __shared__ float tile[32][33];
    const float* Ws[5] = {W0, W1, W2, W3, W4};
    const float* W = Ws[blockIdx.z];
    __nv_bfloat16* hi = wtbase + (size_t)(2 * blockIdx.z)     * W_E;
    __nv_bfloat16* lo = wtbase + (size_t)(2 * blockIdx.z + 1) * W_E;

    int tx = threadIdx.x, ty = threadIdx.y;
    int n0 = blockIdx.x * 32, k0 = blockIdx.y * 32;
#pragma unroll
    for (int r = ty; r < 32; r += 8)
        tile[r][tx] = W[(size_t)(k0 + r) * C_ + n0 + tx];
    __syncthreads();
#pragma unroll
    for (int r = ty; r < 32; r += 8) {
        float v = tile[tx][r];                 // = W[k0+tx][n0+r]
        __nv_bfloat16 h = __float2bfloat16(v);
        size_t o = (size_t)(n0 + r) * C_ + k0 + tx;
        hi[o] = h;
        lo[o] = __float2bfloat16(v - __bfloat162float(h));
    }
}

// ---------------------------------------------------------------------------
// Token-shift mixing fused with fp32 -> (bf16 hi, bf16 lo) split.
// ---------------------------------------------------------------------------
__device__ __forceinline__ void split_store4(__nv_bfloat16* hi, __nv_bfloat16* lo,
                                             size_t idx, float4 o) {
    __nv_bfloat16 h0 = __float2bfloat16(o.x);
    __nv_bfloat16 h1 = __float2bfloat16(o.y);
    __nv_bfloat16 h2 = __float2bfloat16(o.z);
    __nv_bfloat16 h3 = __float2bfloat16(o.w);
    __nv_bfloat162* hp = (__nv_bfloat162*)(hi + idx);
    hp[0] = __nv_bfloat162(h0, h1);
    hp[1] = __nv_bfloat162(h2, h3);
    __nv_bfloat162* lp = (__nv_bfloat162*)(lo + idx);
    lp[0] = __nv_bfloat162(__float2bfloat16(o.x - __bfloat162float(h0)),
                           __float2bfloat16(o.y - __bfloat162float(h1)));
    lp[1] = __nv_bfloat162(__float2bfloat16(o.z - __bfloat162float(h2)),
                           __float2bfloat16(o.w - __bfloat162float(h3)));
}

__global__ __launch_bounds__(256) void mix_split_kernel(
    const float* __restrict__ x,
    const float* __restrict__ tmk, const float* __restrict__ tmv,
    const float* __restrict__ tmr, const float* __restrict__ tmg,
    __nv_bfloat16* __restrict__ xkh, __nv_bfloat16* __restrict__ xkl,
    __nv_bfloat16* __restrict__ xvh, __nv_bfloat16* __restrict__ xvl,
    __nv_bfloat16* __restrict__ xrh, __nv_bfloat16* __restrict__ xrl,
    __nv_bfloat16* __restrict__ xgh, __nv_bfloat16* __restrict__ xgl)
{
    size_t idx4 = (size_t)blockIdx.x * blockDim.x + threadIdx.x;
    size_t idx  = idx4 * 4;
    int    c    = (int)(idx % C_);
    size_t m    = idx / C_;
    int    t    = (int)(m % T_);

    float4 xc = *(const float4*)(x + idx);
    float4 xp = make_float4(0.f, 0.f, 0.f, 0.f);
    if (t != 0) xp = *(const float4*)(x + idx - C_);

    float4 o;
#define DO_MIX(TM, HI, LO)                                                  \
    {                                                                       \
        float4 w4 = *(const float4*)((TM) + c);                             \
        o.x = fmaf(w4.x, xc.x - xp.x, xp.x);                                \
        o.y = fmaf(w4.y, xc.y - xp.y, xp.y);                                \
        o.z = fmaf(w4.z, xc.z - xp.z, xp.z);                                \
        o.w = fmaf(w4.w, xc.w - xp.w, xp.w);                                \
        split_store4(HI, LO, idx, o);                                       \
    }
    DO_MIX(tmk, xkh, xkl)
    DO_MIX(tmv, xvh, xvl)
    DO_MIX(tmr, xrh, xrl)
    DO_MIX(tmg, xgh, xgl)
#undef DO_MIX
}

// ---------------------------------------------------------------------------
// bf16x3 GEMM, batched over blockIdx.z:
//   C_z[M,2048] = A_z[M,2048] @ Bt_z[2048,2048]^T   (fp32 via hi/lo split)
// CTA tile 128x256, warp tile 64x64 (8 warps, 256 thr), BK=32, 3 stages.
// Per chunk: 192 MMAs/warp vs 32 ldsm + 2 barriers.
// ---------------------------------------------------------------------------
#define BM 128
#define BN 256
#define BK 32
#define NCHUNK (2048 / BK)            // 64
#define ROWB 80u                      // 32 bf16 = 64B data, padded to 80B
#define MATA_BYTES (128u * ROWB)      // 10240
#define MATB_BYTES (256u * ROWB)      // 20480
#define STAGE_BYTES (2u * MATA_BYTES + 2u * MATB_BYTES)   // 61440
#define NSTAGE 3
#define GEMM_SMEM (NSTAGE * STAGE_BYTES)   // 184320
#define OFF_AH 0u
#define OFF_AL MATA_BYTES
#define OFF_BH (2u * MATA_BYTES)
#define OFF_BL (2u * MATA_BYTES + MATB_BYTES)

__device__ __forceinline__ void load_stage(
    uint32_t sstage, int k0, int tid, int m0, int n0,
    const __nv_bfloat16* Ah, const __nv_bfloat16* Al,
    const __nv_bfloat16* Bh, const __nv_bfloat16* Bl)
{
#pragma unroll
    for (int j = 0; j < 12; j++) {
        int id = tid + 256 * j;         // 0..3071
        const __nv_bfloat16* base;
        uint32_t roff;
        int cc, grow0;
        if (id < 512)        { cc = id;        base = Ah; roff = OFF_AH; grow0 = m0; }
        else if (id < 1024)  { cc = id - 512;  base = Al; roff = OFF_AL; grow0 = m0; }
        else if (id < 2048)  { cc = id - 1024; base = Bh; roff = OFF_BH; grow0 = n0; }
        else                 { cc = id - 2048; base = Bl; roff = OFF_BL; grow0 = n0; }
        int row = cc >> 2, ch = cc & 3;
        const void* gp = base + (size_t)(grow0 + row) * 2048 + k0 + ch * 8;
        uint32_t so = sstage + roff + (uint32_t)row * ROWB + (uint32_t)ch * 16u;
        cp16(so, gp);
    }
    CP_COMMIT();
}

__global__ __launch_bounds__(256, 1) void gemm_bf16x3(
    const __nv_bfloat16* __restrict__ actb,
    const __nv_bfloat16* __restrict__ wtb,
    float* __restrict__ outb, int epi_z)
{
    extern __shared__ __align__(128) unsigned char dsm[];
    const uint32_t sb = smem_u32(dsm);

    const int z = blockIdx.z;
    const __nv_bfloat16* Ah = actb + (size_t)(2 * z) * ACT_E;
    const __nv_bfloat16* Al = Ah + ACT_E;
    const __nv_bfloat16* Bh = wtb + (size_t)(2 * z) * W_E;
    const __nv_bfloat16* Bl = Bh + W_E;
    float* Cm = outb + (size_t)z * ACT_E;
    const int epi = (z == epi_z);

    const int tid  = threadIdx.x;
    const int wid  = tid >> 5;
    const int lane = tid & 31;
    const int wm   = wid >> 2;          // 0..1 -> warp M origin wm*64
    const int wn   = wid & 3;           // 0..3 -> warp N origin wn*64
    const int m0   = blockIdx.y * BM;
    const int n0   = blockIdx.x * BN;

    float acc[4][8][4];
#pragma unroll
    for (int i = 0; i < 4; i++)
#pragma unroll
        for (int j = 0; j < 8; j++)
#pragma unroll
            for (int q = 0; q < 4; q++) acc[i][j][q] = 0.f;

    const int a_r  = (lane & 15);
    const int a_kb = (lane >> 4) * 16;
    const int b_r  = (lane & 7) + ((lane >> 4) * 8);
    const int b_kb = ((lane >> 3) & 1) * 16;

    // prologue: fill all 3 stages
    load_stage(sb + 0 * STAGE_BYTES, 0 * BK, tid, m0, n0, Ah, Al, Bh, Bl);
    load_stage(sb + 1 * STAGE_BYTES, 1 * BK, tid, m0, n0, Ah, Al, Bh, Bl);
    load_stage(sb + 2 * STAGE_BYTES, 2 * BK, tid, m0, n0, Ah, Al, Bh, Bl);

    for (int i = 0; i < NCHUNK; i++) {
        const uint32_t st = sb + (uint32_t)(i % 3) * STAGE_BYTES;
        CP_WAIT2();               // stage i complete (i+1, i+2 may be pending)
        __syncthreads();

        uint32_t ah[4][4], al[4][4], bh[8][2], bl[8][2];

        // ---- ks = 0 : load frags, compute ----
#pragma unroll
        for (int mi = 0; mi < 4; mi++) {
            uint32_t ao = (uint32_t)(wm * 64 + mi * 16 + a_r) * ROWB + (uint32_t)a_kb;
            ldsm4(ah[mi][0], ah[mi][1], ah[mi][2], ah[mi][3], st + OFF_AH + ao);
            ldsm4(al[mi][0], al[mi][1], al[mi][2], al[mi][3], st + OFF_AL + ao);
        }
#pragma unroll
        for (int bi = 0; bi < 4; bi++) {
            uint32_t bo = (uint32_t)(wn * 64 + bi * 16 + b_r) * ROWB + (uint32_t)b_kb;
            uint32_t t0, t1, t2, t3;
            ldsm4(t0, t1, t2, t3, st + OFF_BH + bo);
            bh[bi * 2][0] = t0; bh[bi * 2][1] = t1;
            bh[bi * 2 + 1][0] = t2; bh[bi * 2 + 1][1] = t3;
            ldsm4(t0, t1, t2, t3, st + OFF_BL + bo);
            bl[bi * 2][0] = t0; bl[bi * 2][1] = t1;
            bl[bi * 2 + 1][0] = t2; bl[bi * 2 + 1][1] = t3;
        }
#pragma unroll
        for (int mi = 0; mi < 4; mi++)
#pragma unroll
            for (int ng = 0; ng < 8; ng++) {
                mma16816(acc[mi][ng], ah[mi], bh[ng]);
                mma16816(acc[mi][ng], ah[mi], bl[ng]);
                mma16816(acc[mi][ng], al[mi], bh[ng]);
            }

        // ---- ks = 1 : load frags, release stage, refill, compute ----
#pragma unroll
        for (int mi = 0; mi < 4; mi++) {
            uint32_t ao = (uint32_t)(wm * 64 + mi * 16 + a_r) * ROWB + (uint32_t)(32 + a_kb);
            ldsm4(ah[mi][0], ah[mi][1], ah[mi][2], ah[mi][3], st + OFF_AH + ao);
            ldsm4(al[mi][0], al[mi][1], al[mi][2], al[mi][3], st + OFF_AL + ao);
        }
#pragma unroll
        for (int bi = 0; bi < 4; bi++) {
            uint32_t bo = (uint32_t)(wn * 64 + bi * 16 + b_r) * ROWB + (uint32_t)(32 + b_kb);
            uint32_t t0, t1, t2, t3;
            ldsm4(t0, t1, t2, t3, st + OFF_BH + bo);
            bh[bi * 2][0] = t0; bh[bi * 2][1] = t1;
            bh[bi * 2 + 1][0] = t2; bh[bi * 2 + 1][1] = t3;
            ldsm4(t0, t1, t2, t3, st + OFF_BL + bo);
            bl[bi * 2][0] = t0; bl[bi * 2][1] = t1;
            bl[bi * 2 + 1][0] = t2; bl[bi * 2 + 1][1] = t3;
        }
        __syncthreads();          // all warps done reading stage i
        if (i + 3 < NCHUNK)
            load_stage(st, (i + 3) * BK, tid, m0, n0, Ah, Al, Bh, Bl);
        else
            CP_COMMIT();          // keep wait_group accounting uniform
#pragma unroll
        for (int mi = 0; mi < 4; mi++)
#pragma unroll
            for (int ng = 0; ng < 8; ng++) {
                mma16816(acc[mi][ng], ah[mi], bh[ng]);
                mma16816(acc[mi][ng], ah[mi], bl[ng]);
                mma16816(acc[mi][ng], al[mi], bh[ng]);
            }
    }
    CP_WAIT0();

    // epilogue
#pragma unroll
    for (int mi = 0; mi < 4; mi++) {
        int row0 = m0 + wm * 64 + mi * 16 + (lane >> 2);
#pragma unroll
        for (int ng = 0; ng < 8; ng++) {
            int col = n0 + wn * 64 + ng * 8 + (lane & 3) * 2;
            float2 v0 = make_float2(acc[mi][ng][0], acc[mi][ng][1]);
            float2 v1 = make_float2(acc[mi][ng][2], acc[mi][ng][3]);
            if (epi) {
                v0.x = v0.x / (1.f + expf(-v0.x));
                v0.y = v0.y / (1.f + expf(-v0.y));
                v1.x = v1.x / (1.f + expf(-v1.x));
                v1.y = v1.y / (1.f + expf(-v1.y));
            }
            *(float2*)(Cm + (size_t)row0 * 2048 + col)       = v0;
            *(float2*)(Cm + (size_t)(row0 + 8) * 2048 + col) = v1;
        }
    }
}

// ---------------------------------------------------------------------------
// WKV5 recurrence, 2-way split over state rows. 128 threads per (b,h).
// ---------------------------------------------------------------------------
#define CH 16
__global__ __launch_bounds__(128) void wkv_kernel(
    const float* __restrict__ r, const float* __restrict__ k,
    const float* __restrict__ v, const float* __restrict__ decay,
    const float* __restrict__ faaaa, float* __restrict__ y)
{
    const int bh   = blockIdx.x;
    const int b    = bh / H_;
    const int h    = bh % H_;
    const int tid  = threadIdx.x;
    const int j    = tid & 63;
    const int half = tid >> 6;          // 0 or 1
    const int i0   = half * 32;

    __shared__ float rs[CH][HS_], ks_[CH][HS_], vs[CH][HS_];
    __shared__ float part[CH][HS_];
    __shared__ float cpart[2][CH];
    __shared__ float ws[HS_], us[HS_];

    if (half == 0) {
        ws[j] = expf(-expf(decay[h * HS_ + j]));
        us[j] = faaaa[h * HS_ + j];
    }

    float S[32];
#pragma unroll
    for (int i = 0; i < 32; i++) S[i] = 0.f;

    const size_t base = (size_t)b * T_ * C_ + h * HS_;

    for (int t0 = 0; t0 < T_; t0 += CH) {
        __syncthreads();                // smem reuse guard (also covers ws/us init)
#pragma unroll
        for (int ss = 0; ss < 8; ss++) {
            int s = half * 8 + ss;
            size_t off = base + (size_t)(t0 + s) * C_ + j;
            rs[s][j]  = r[off];
            ks_[s][j] = k[off];
            vs[s][j]  = v[off];
        }
        __syncthreads();
        if (j < CH) {                   // per-half partial of c_t
            float c = 0.f;
#pragma unroll
            for (int i = 0; i < 32; i++)
                c = fmaf(rs[j][i0 + i] * us[i0 + i], ks_[j][i0 + i], c);
            cpart[half][j] = c;
        }
        __syncthreads();

        float yy[CH];
        for (int s = 0; s < CH; s++) {
            float vj  = vs[s][j];
            float acc = 0.f;
#pragma unroll
            for (int i = 0; i < 32; i++) {
                acc  = fmaf(rs[s][i0 + i], S[i], acc);   // uses S before update
                S[i] = fmaf(ws[i0 + i], S[i], ks_[s][i0 + i] * vj);
            }
            yy[s] = acc;
        }
        if (half == 1) {
#pragma unroll
            for (int s = 0; s < CH; s++) part[s][j] = yy[s];
        }
        __syncthreads();
        if (half == 0) {
#pragma unroll
            for (int s = 0; s < CH; s++) {
                float c = cpart[0][s] + cpart[1][s];
                y[base + (size_t)(t0 + s) * C_ + j] =
                    yy[s] + part[s][j] + c * vs[s][j];
            }
        }
    }
}
#undef CH

// ---------------------------------------------------------------------------
// GroupNorm (/8, per head) * gate, output split to bf16 hi/lo for Wo GEMM.
// ---------------------------------------------------------------------------
__global__ __launch_bounds__(256) void gnorm_kernel(
    const float* __restrict__ y, const float* __restrict__ g,
    const float* __restrict__ lnw, const float* __restrict__ lnb,
    __nv_bfloat16* __restrict__ zh, __nv_bfloat16* __restrict__ zl)
{
    int warp = blockIdx.x * 8 + (threadIdx.x >> 5);
    int lane = threadIdx.x & 31;
    int row  = warp / H_;
    int h    = warp % H_;

    const size_t o0 = (size_t)row * C_ + h * HS_ + lane;
    float a0 = y[o0]      * 0.125f;
    float a1 = y[o0 + 32] * 0.125f;

    float s = a0 + a1;
#pragma unroll
    for (int o = 16; o; o >>= 1) s += __shfl_xor_sync(0xffffffffu, s, o);
    float mean = s * (1.f / 64.f);

    float d0 = a0 - mean, d1 = a1 - mean;
    float q = d0 * d0 + d1 * d1;
#pragma unroll
    for (int o = 16; o; o >>= 1) q += __shfl_xor_sync(0xffffffffu, q, o);
    float inv = rsqrtf(q * (1.f / 64.f) + 1e-5f);

    int c = h * HS_ + lane;
    float z0 = fmaf(d0 * inv, lnw[c],      lnb[c])      * g[o0];
    float z1 = fmaf(d1 * inv, lnw[c + 32], lnb[c + 32]) * g[o0 + 32];

    __nv_bfloat16 h0 = __float2bfloat16(z0);
    __nv_bfloat16 h1 = __float2bfloat16(z1);
    zh[o0]      = h0;
    zh[o0 + 32] = h1;
    zl[o0]      = __float2bfloat16(z0 - __bfloat162float(h0));
    zl[o0 + 32] = __float2bfloat16(z1 - __bfloat162float(h1));
}

// ---------------------------------------------------------------------------
extern "C" void kernel_launch(void* const* d_in, const int* in_sizes, int n_in,
                              void* d_out, int out_size)
{
    const float* x   = (const float*)d_in[0];
    const float* tmk = (const float*)d_in[1];
    const float* tmv = (const float*)d_in[2];
    const float* tmr = (const float*)d_in[3];
    const float* tmg = (const float*)d_in[4];
    const float* dec = (const float*)d_in[5];
    const float* faa = (const float*)d_in[6];
    const float* Wr  = (const float*)d_in[7];
    const float* Wk  = (const float*)d_in[8];
    const float* Wv  = (const float*)d_in[9];
    const float* Wg  = (const float*)d_in[10];
    const float* Wo  = (const float*)d_in[11];
    const float* lnw = (const float*)d_in[12];
    const float* lnb = (const float*)d_in[13];
    float* out = (float*)d_out;

    unsigned char* sc = nullptr;
    cudaGetSymbolAddress((void**)&sc, g_scratch);

    // activation order matches GEMM batch z: r, k, v, g (hi/lo pairs)
    __nv_bfloat16* actb = (__nv_bfloat16*)sc;
    __nv_bfloat16* act[8];
    for (int i = 0; i < 8; i++) act[i] = actb + (size_t)i * ACT_E;
    __nv_bfloat16* wtbase = (__nv_bfloat16*)(sc + 8 * ACT_BB);
    __nv_bfloat16* wt[10];   // wr, wk, wv, wg, wo (hi/lo pairs)
    for (int i = 0; i < 10; i++) wt[i] = wtbase + (size_t)i * W_E;
    float* f32b = (float*)(sc + 8 * ACT_BB + 10 * W_BB);   // r,k,v,g outputs
    float* rb = f32b + 0 * ACT_E;
    float* kb = f32b + 1 * ACT_E;
    float* vb = f32b + 2 * ACT_E;
    float* gb = f32b + 3 * ACT_E;
    float* yb = (float*)act[0];          // aliases xr hi+lo (dead after GEMMs)
    __nv_bfloat16* zh = act[2];          // aliases xk_hi (dead after GEMMs)
    __nv_bfloat16* zl = act[3];          // aliases xk_lo (contiguous pair)

    cudaFuncSetAttribute(gemm_bf16x3, cudaFuncAttributeMaxDynamicSharedMemorySize, GEMM_SMEM);

    // launch 1: fused weight split (order r,k,v,g,o)
    dim3 wgrid(64, 64, 5);
    dim3 wblk(32, 8);
    wsplit_all_kernel<<<wgrid, wblk>>>(Wr, Wk, Wv, Wg, Wo, wtbase);

    // launch 2: mixing (act order: r, k, v, g)
    mix_split_kernel<<<32768, 256>>>(x, tmk, tmv, tmr, tmg,
                                     act[2], act[3], act[4], act[5],
                                     act[0], act[1], act[6], act[7]);

    // launch 3: batched r/k/v/g GEMMs (z=3 gets silu epilogue)
    dim3 ggrid(C_ / BN, M_ / BM, 4);   // (8, 128, 4)
    gemm_bf16x3<<<ggrid, 256, GEMM_SMEM>>>(actb, wtbase, f32b, 3);

    // launch 4: wkv
    wkv_kernel<<<256, 128>>>(rb, kb, vb, dec, faa, yb);

    // launch 5: groupnorm * gate -> bf16 split
    gnorm_kernel<<<65536, 256>>>(yb, gb, lnw, lnb, zh, zl);

    // launch 6 (profiled): Wo GEMM
    dim3 ogrid(C_ / BN, M_ / BM, 1);
    gemm_bf16x3<<<ogrid, 256, GEMM_SMEM>>>(zh, wt[8], out, -1);
}

// round 13
// speedup vs baseline: 1.3152x; 1.0150x over previous
#include <cuda_runtime.h>
#include <cuda_bf16.h>
#include <math.h>
#include <stdint.h>

#define B_  8
#define T_  2048
#define C_  2048
#define HS_ 64
#define H_  32
#define M_  (B_*T_)   // 16384

// ---------------------------------------------------------------------------
// Static scratch
// ---------------------------------------------------------------------------
#define ACT_E   ((size_t)M_ * C_)          // 33,554,432 elems
#define ACT_BB  (ACT_E * 2)                // 64 MiB per bf16 act buffer
#define W_E     ((size_t)C_ * C_)
#define W_BB    (W_E * 2)                  // 8 MiB per bf16 weight buffer
#define F32_B   (ACT_E * 4)                // 128 MiB per fp32 buffer

__device__ __align__(256) unsigned char g_scratch[8 * ACT_BB + 10 * W_BB + 4 * F32_B];

// ---------------------------------------------------------------------------
// PTX helpers (plain sm_80 PTX — valid under compute_103)
// ---------------------------------------------------------------------------
__device__ __forceinline__ uint32_t smem_u32(const void* p) {
    uint32_t a;
    asm("{ .reg .u64 t; cvta.to.shared.u64 t, %1; cvt.u32.u64 %0, t; }" : "=r"(a) : "l"(p));
    return a;
}

__device__ __forceinline__ void cp16(uint32_t so, const void* gp) {
    asm volatile("cp.async.cg.shared.global [%0], [%1], 16;" :: "r"(so), "l"(gp));
}
#define CP_COMMIT() asm volatile("cp.async.commit_group;" ::: "memory")
#define CP_WAIT2()  asm volatile("cp.async.wait_group 2;" ::: "memory")
#define CP_WAIT0()  asm volatile("cp.async.wait_group 0;" ::: "memory")

__device__ __forceinline__ void ldsm4(uint32_t& r0, uint32_t& r1, uint32_t& r2, uint32_t& r3,
                                      uint32_t addr) {
    asm volatile("ldmatrix.sync.aligned.m8n8.x4.shared.b16 {%0,%1,%2,%3}, [%4];"
                 : "=r"(r0), "=r"(r1), "=r"(r2), "=r"(r3) : "r"(addr));
}

__device__ __forceinline__ void mma16816(float* c, const uint32_t* a, const uint32_t* b) {
    asm("mma.sync.aligned.m16n8k16.row.col.f32.bf16.bf16.f32 "
        "{%0,%1,%2,%3}, {%4,%5,%6,%7}, {%8,%9}, {%0,%1,%2,%3};"
        : "+f"(c[0]), "+f"(c[1]), "+f"(c[2]), "+f"(c[3])
        : "r"(a[0]), "r"(a[1]), "r"(a[2]), "r"(a[3]), "r"(b[0]), "r"(b[1]));
}

// ---------------------------------------------------------------------------
// Fused weight transpose + split (all 5 weights, blockIdx.z selects).
// ---------------------------------------------------------------------------
__global__ __launch_bounds__(256) void wsplit_all_kernel(
    const float* __restrict__ W0, const float* __restrict__ W1,
    const float* __restrict__ W2, const float* __restrict__ W3,
    const float* __restrict__ W4,
    __nv_bfloat16* __restrict__ wtbase)
{
    __shared__ float tile[32][33];
    const float* Ws[5] = {W0, W1, W2, W3, W4};
    const float* W = Ws[blockIdx.z];
    __nv_bfloat16* hi = wtbase + (size_t)(2 * blockIdx.z)     * W_E;
    __nv_bfloat16* lo = wtbase + (size_t)(2 * blockIdx.z + 1) * W_E;

    int tx = threadIdx.x, ty = threadIdx.y;
    int n0 = blockIdx.x * 32, k0 = blockIdx.y * 32;
#pragma unroll
    for (int r = ty; r < 32; r += 8)
        tile[r][tx] = W[(size_t)(k0 + r) * C_ + n0 + tx];
    __syncthreads();
#pragma unroll
    for (int r = ty; r < 32; r += 8) {
        float v = tile[tx][r];                 // = W[k0+tx][n0+r]
        __nv_bfloat16 h = __float2bfloat16(v);
        size_t o = (size_t)(n0 + r) * C_ + k0 + tx;
        hi[o] = h;
        lo[o] = __float2bfloat16(v - __bfloat162float(h));
    }
}

// ---------------------------------------------------------------------------
// Token-shift mixing fused with fp32 -> (bf16 hi, bf16 lo) split.
// ---------------------------------------------------------------------------
__device__ __forceinline__ void split_store4(__nv_bfloat16* hi, __nv_bfloat16* lo,
                                             size_t idx, float4 o) {
    __nv_bfloat16 h0 = __float2bfloat16(o.x);
    __nv_bfloat16 h1 = __float2bfloat16(o.y);
    __nv_bfloat16 h2 = __float2bfloat16(o.z);
    __nv_bfloat16 h3 = __float2bfloat16(o.w);
    __nv_bfloat162* hp = (__nv_bfloat162*)(hi + idx);
    hp[0] = __nv_bfloat162(h0, h1);
    hp[1] = __nv_bfloat162(h2, h3);
    __nv_bfloat162* lp = (__nv_bfloat162*)(lo + idx);
    lp[0] = __nv_bfloat162(__float2bfloat16(o.x - __bfloat162float(h0)),
                           __float2bfloat16(o.y - __bfloat162float(h1)));
    lp[1] = __nv_bfloat162(__float2bfloat16(o.z - __bfloat162float(h2)),
                           __float2bfloat16(o.w - __bfloat162float(h3)));
}

__global__ __launch_bounds__(256) void mix_split_kernel(
    const float* __restrict__ x,
    const float* __restrict__ tmk, const float* __restrict__ tmv,
    const float* __restrict__ tmr, const float* __restrict__ tmg,
    __nv_bfloat16* __restrict__ xkh, __nv_bfloat16* __restrict__ xkl,
    __nv_bfloat16* __restrict__ xvh, __nv_bfloat16* __restrict__ xvl,
    __nv_bfloat16* __restrict__ xrh, __nv_bfloat16* __restrict__ xrl,
    __nv_bfloat16* __restrict__ xgh, __nv_bfloat16* __restrict__ xgl)
{
    size_t idx4 = (size_t)blockIdx.x * blockDim.x + threadIdx.x;
    size_t idx  = idx4 * 4;
    int    c    = (int)(idx % C_);
    size_t m    = idx / C_;
    int    t    = (int)(m % T_);

    float4 xc = *(const float4*)(x + idx);
    float4 xp = make_float4(0.f, 0.f, 0.f, 0.f);
    if (t != 0) xp = *(const float4*)(x + idx - C_);

    float4 o;
#define DO_MIX(TM, HI, LO)                                                  \
    {                                                                       \
        float4 w4 = *(const float4*)((TM) + c);                             \
        o.x = fmaf(w4.x, xc.x - xp.x, xp.x);                                \
        o.y = fmaf(w4.y, xc.y - xp.y, xp.y);                                \
        o.z = fmaf(w4.z, xc.z - xp.z, xp.z);                                \
        o.w = fmaf(w4.w, xc.w - xp.w, xp.w);                                \
        split_store4(HI, LO, idx, o);                                       \
    }
    DO_MIX(tmk, xkh, xkl)
    DO_MIX(tmv, xvh, xvl)
    DO_MIX(tmr, xrh, xrl)
    DO_MIX(tmg, xgh, xgl)
#undef DO_MIX
}

// ---------------------------------------------------------------------------
// bf16x3 GEMM, batched over blockIdx.z (unchanged from R12 WIN config):
// CTA tile 128x256, warp tile 64x64 (8 warps, 256 thr), BK=32, 3 stages.
// ---------------------------------------------------------------------------
#define BM 128
#define BN 256
#define BK 32
#define NCHUNK (2048 / BK)            // 64
#define ROWB 80u                      // 32 bf16 = 64B data, padded to 80B
#define MATA_BYTES (128u * ROWB)      // 10240
#define MATB_BYTES (256u * ROWB)      // 20480
#define STAGE_BYTES (2u * MATA_BYTES + 2u * MATB_BYTES)   // 61440
#define NSTAGE 3
#define GEMM_SMEM (NSTAGE * STAGE_BYTES)   // 184320
#define OFF_AH 0u
#define OFF_AL MATA_BYTES
#define OFF_BH (2u * MATA_BYTES)
#define OFF_BL (2u * MATA_BYTES + MATB_BYTES)

__device__ __forceinline__ void load_stage(
    uint32_t sstage, int k0, int tid, int m0, int n0,
    const __nv_bfloat16* Ah, const __nv_bfloat16* Al,
    const __nv_bfloat16* Bh, const __nv_bfloat16* Bl)
{
#pragma unroll
    for (int j = 0; j < 12; j++) {
        int id = tid + 256 * j;         // 0..3071
        const __nv_bfloat16* base;
        uint32_t roff;
        int cc, grow0;
        if (id < 512)        { cc = id;        base = Ah; roff = OFF_AH; grow0 = m0; }
        else if (id < 1024)  { cc = id - 512;  base = Al; roff = OFF_AL; grow0 = m0; }
        else if (id < 2048)  { cc = id - 1024; base = Bh; roff = OFF_BH; grow0 = n0; }
        else                 { cc = id - 2048; base = Bl; roff = OFF_BL; grow0 = n0; }
        int row = cc >> 2, ch = cc & 3;
        const void* gp = base + (size_t)(grow0 + row) * 2048 + k0 + ch * 8;
        uint32_t so = sstage + roff + (uint32_t)row * ROWB + (uint32_t)ch * 16u;
        cp16(so, gp);
    }
    CP_COMMIT();
}

__global__ __launch_bounds__(256, 1) void gemm_bf16x3(
    const __nv_bfloat16* __restrict__ actb,
    const __nv_bfloat16* __restrict__ wtb,
    float* __restrict__ outb, int epi_z)
{
    extern __shared__ __align__(128) unsigned char dsm[];
    const uint32_t sb = smem_u32(dsm);

    const int z = blockIdx.z;
    const __nv_bfloat16* Ah = actb + (size_t)(2 * z) * ACT_E;
    const __nv_bfloat16* Al = Ah + ACT_E;
    const __nv_bfloat16* Bh = wtb + (size_t)(2 * z) * W_E;
    const __nv_bfloat16* Bl = Bh + W_E;
    float* Cm = outb + (size_t)z * ACT_E;
    const int epi = (z == epi_z);

    const int tid  = threadIdx.x;
    const int wid  = tid >> 5;
    const int lane = tid & 31;
    const int wm   = wid >> 2;          // 0..1 -> warp M origin wm*64
    const int wn   = wid & 3;           // 0..3 -> warp N origin wn*64
    const int m0   = blockIdx.y * BM;
    const int n0   = blockIdx.x * BN;

    float acc[4][8][4];
#pragma unroll
    for (int i = 0; i < 4; i++)
#pragma unroll
        for (int j = 0; j < 8; j++)
#pragma unroll
            for (int q = 0; q < 4; q++) acc[i][j][q] = 0.f;

    const int a_r  = (lane & 15);
    const int a_kb = (lane >> 4) * 16;
    const int b_r  = (lane & 7) + ((lane >> 4) * 8);
    const int b_kb = ((lane >> 3) & 1) * 16;

    // prologue: fill all 3 stages
    load_stage(sb + 0 * STAGE_BYTES, 0 * BK, tid, m0, n0, Ah, Al, Bh, Bl);
    load_stage(sb + 1 * STAGE_BYTES, 1 * BK, tid, m0, n0, Ah, Al, Bh, Bl);
    load_stage(sb + 2 * STAGE_BYTES, 2 * BK, tid, m0, n0, Ah, Al, Bh, Bl);

    for (int i = 0; i < NCHUNK; i++) {
        const uint32_t st = sb + (uint32_t)(i % 3) * STAGE_BYTES;
        CP_WAIT2();               // stage i complete (i+1, i+2 may be pending)
        __syncthreads();

        uint32_t ah[4][4], al[4][4], bh[8][2], bl[8][2];

        // ---- ks = 0 : load frags, compute ----
#pragma unroll
        for (int mi = 0; mi < 4; mi++) {
            uint32_t ao = (uint32_t)(wm * 64 + mi * 16 + a_r) * ROWB + (uint32_t)a_kb;
            ldsm4(ah[mi][0], ah[mi][1], ah[mi][2], ah[mi][3], st + OFF_AH + ao);
            ldsm4(al[mi][0], al[mi][1], al[mi][2], al[mi][3], st + OFF_AL + ao);
        }
#pragma unroll
        for (int bi = 0; bi < 4; bi++) {
            uint32_t bo = (uint32_t)(wn * 64 + bi * 16 + b_r) * ROWB + (uint32_t)b_kb;
            uint32_t t0, t1, t2, t3;
            ldsm4(t0, t1, t2, t3, st + OFF_BH + bo);
            bh[bi * 2][0] = t0; bh[bi * 2][1] = t1;
            bh[bi * 2 + 1][0] = t2; bh[bi * 2 + 1][1] = t3;
            ldsm4(t0, t1, t2, t3, st + OFF_BL + bo);
            bl[bi * 2][0] = t0; bl[bi * 2][1] = t1;
            bl[bi * 2 + 1][0] = t2; bl[bi * 2 + 1][1] = t3;
        }
#pragma unroll
        for (int mi = 0; mi < 4; mi++)
#pragma unroll
            for (int ng = 0; ng < 8; ng++) {
                mma16816(acc[mi][ng], ah[mi], bh[ng]);
                mma16816(acc[mi][ng], ah[mi], bl[ng]);
                mma16816(acc[mi][ng], al[mi], bh[ng]);
            }

        // ---- ks = 1 : load frags, release stage, refill, compute ----
#pragma unroll
        for (int mi = 0; mi < 4; mi++) {
            uint32_t ao = (uint32_t)(wm * 64 + mi * 16 + a_r) * ROWB + (uint32_t)(32 + a_kb);
            ldsm4(ah[mi][0], ah[mi][1], ah[mi][2], ah[mi][3], st + OFF_AH + ao);
            ldsm4(al[mi][0], al[mi][1], al[mi][2], al[mi][3], st + OFF_AL + ao);
        }
#pragma unroll
        for (int bi = 0; bi < 4; bi++) {
            uint32_t bo = (uint32_t)(wn * 64 + bi * 16 + b_r) * ROWB + (uint32_t)(32 + b_kb);
            uint32_t t0, t1, t2, t3;
            ldsm4(t0, t1, t2, t3, st + OFF_BH + bo);
            bh[bi * 2][0] = t0; bh[bi * 2][1] = t1;
            bh[bi * 2 + 1][0] = t2; bh[bi * 2 + 1][1] = t3;
            ldsm4(t0, t1, t2, t3, st + OFF_BL + bo);
            bl[bi * 2][0] = t0; bl[bi * 2][1] = t1;
            bl[bi * 2 + 1][0] = t2; bl[bi * 2 + 1][1] = t3;
        }
        __syncthreads();          // all warps done reading stage i
        if (i + 3 < NCHUNK)
            load_stage(st, (i + 3) * BK, tid, m0, n0, Ah, Al, Bh, Bl);
        else
            CP_COMMIT();          // keep wait_group accounting uniform
#pragma unroll
        for (int mi = 0; mi < 4; mi++)
#pragma unroll
            for (int ng = 0; ng < 8; ng++) {
                mma16816(acc[mi][ng], ah[mi], bh[ng]);
                mma16816(acc[mi][ng], ah[mi], bl[ng]);
                mma16816(acc[mi][ng], al[mi], bh[ng]);
            }
    }
    CP_WAIT0();

    // epilogue
#pragma unroll
    for (int mi = 0; mi < 4; mi++) {
        int row0 = m0 + wm * 64 + mi * 16 + (lane >> 2);
#pragma unroll
        for (int ng = 0; ng < 8; ng++) {
            int col = n0 + wn * 64 + ng * 8 + (lane & 3) * 2;
            float2 v0 = make_float2(acc[mi][ng][0], acc[mi][ng][1]);
            float2 v1 = make_float2(acc[mi][ng][2], acc[mi][ng][3]);
            if (epi) {
                v0.x = v0.x / (1.f + expf(-v0.x));
                v0.y = v0.y / (1.f + expf(-v0.y));
                v1.x = v1.x / (1.f + expf(-v1.x));
                v1.y = v1.y / (1.f + expf(-v1.y));
            }
            *(float2*)(Cm + (size_t)row0 * 2048 + col)       = v0;
            *(float2*)(Cm + (size_t)(row0 + 8) * 2048 + col) = v1;
        }
    }
}

// ---------------------------------------------------------------------------
// WKV5 recurrence, 4-way split over state rows. 256 threads per (b,h):
// thread (j, q) owns S[i][j] for i in [q*16, q*16+16).
// y_j(t) = sum_i r_i*S_ij + v_j * c_t,  c_t = sum_i r_i*u_i*k_i.
// Quarters 1-3 push y partials through smem; quarter 0 reduces + stores.
// ---------------------------------------------------------------------------
#define CH 16
__global__ __launch_bounds__(256) void wkv_kernel(
    const float* __restrict__ r, const float* __restrict__ k,
    const float* __restrict__ v, const float* __restrict__ decay,
    const float* __restrict__ faaaa, float* __restrict__ y)
{
    const int bh  = blockIdx.x;
    const int b   = bh / H_;
    const int h   = bh % H_;
    const int tid = threadIdx.x;
    const int j   = tid & 63;
    const int q   = tid >> 6;           // 0..3
    const int i0  = q * 16;

    __shared__ float rs[CH][HS_], ks_[CH][HS_], vs[CH][HS_];
    __shared__ float part[3][CH][HS_];
    __shared__ float cpart[4][CH];
    __shared__ float ws[HS_], us[HS_];

    if (q == 0) {
        ws[j] = expf(-expf(decay[h * HS_ + j]));
        us[j] = faaaa[h * HS_ + j];
    }

    float S[16];
#pragma unroll
    for (int i = 0; i < 16; i++) S[i] = 0.f;

    const size_t base = (size_t)b * T_ * C_ + h * HS_;

    for (int t0 = 0; t0 < T_; t0 += CH) {
        __syncthreads();                // smem reuse guard (also covers ws/us init)
#pragma unroll
        for (int ss = 0; ss < 4; ss++) {
            int s = q * 4 + ss;
            size_t off = base + (size_t)(t0 + s) * C_ + j;
            rs[s][j]  = r[off];
            ks_[s][j] = k[off];
            vs[s][j]  = v[off];
        }
        __syncthreads();
        if (j < CH) {                   // per-quarter partial of c_t
            float c = 0.f;
#pragma unroll
            for (int i = 0; i < 16; i++)
                c = fmaf(rs[j][i0 + i] * us[i0 + i], ks_[j][i0 + i], c);
            cpart[q][j] = c;
        }
        __syncthreads();

        float yy[CH];
        for (int s = 0; s < CH; s++) {
            float vj  = vs[s][j];
            float acc = 0.f;
#pragma unroll
            for (int i = 0; i < 16; i++) {
                acc  = fmaf(rs[s][i0 + i], S[i], acc);   // uses S before update
                S[i] = fmaf(ws[i0 + i], S[i], ks_[s][i0 + i] * vj);
            }
            yy[s] = acc;
        }
        if (q != 0) {
#pragma unroll
            for (int s = 0; s < CH; s++) part[q - 1][s][j] = yy[s];
        }
        __syncthreads();
        if (q == 0) {
#pragma unroll
            for (int s = 0; s < CH; s++) {
                float c = (cpart[0][s] + cpart[1][s]) + (cpart[2][s] + cpart[3][s]);
                float sum = yy[s] + part[0][s][j] + part[1][s][j] + part[2][s][j];
                y[base + (size_t)(t0 + s) * C_ + j] = sum + c * vs[s][j];
            }
        }
    }
}
#undef CH

// ---------------------------------------------------------------------------
// GroupNorm (/8, per head) * gate, output split to bf16 hi/lo for Wo GEMM.
// ---------------------------------------------------------------------------
__global__ __launch_bounds__(256) void gnorm_kernel(
    const float* __restrict__ y, const float* __restrict__ g,
    const float* __restrict__ lnw, const float* __restrict__ lnb,
    __nv_bfloat16* __restrict__ zh, __nv_bfloat16* __restrict__ zl)
{
    int warp = blockIdx.x * 8 + (threadIdx.x >> 5);
    int lane = threadIdx.x & 31;
    int row  = warp / H_;
    int h    = warp % H_;

    const size_t o0 = (size_t)row * C_ + h * HS_ + lane;
    float a0 = y[o0]      * 0.125f;
    float a1 = y[o0 + 32] * 0.125f;

    float s = a0 + a1;
#pragma unroll
    for (int o = 16; o; o >>= 1) s += __shfl_xor_sync(0xffffffffu, s, o);
    float mean = s * (1.f / 64.f);

    float d0 = a0 - mean, d1 = a1 - mean;
    float q = d0 * d0 + d1 * d1;
#pragma unroll
    for (int o = 16; o; o >>= 1) q += __shfl_xor_sync(0xffffffffu, q, o);
    float inv = rsqrtf(q * (1.f / 64.f) + 1e-5f);

    int c = h * HS_ + lane;
    float z0 = fmaf(d0 * inv, lnw[c],      lnb[c])      * g[o0];
    float z1 = fmaf(d1 * inv, lnw[c + 32], lnb[c + 32]) * g[o0 + 32];

    __nv_bfloat16 h0 = __float2bfloat16(z0);
    __nv_bfloat16 h1 = __float2bfloat16(z1);
    zh[o0]      = h0;
    zh[o0 + 32] = h1;
    zl[o0]      = __float2bfloat16(z0 - __bfloat162float(h0));
    zl[o0 + 32] = __float2bfloat16(z1 - __bfloat162float(h1));
}

// ---------------------------------------------------------------------------
extern "C" void kernel_launch(void* const* d_in, const int* in_sizes, int n_in,
                              void* d_out, int out_size)
{
    const float* x   = (const float*)d_in[0];
    const float* tmk = (const float*)d_in[1];
    const float* tmv = (const float*)d_in[2];
    const float* tmr = (const float*)d_in[3];
    const float* tmg = (const float*)d_in[4];
    const float* dec = (const float*)d_in[5];
    const float* faa = (const float*)d_in[6];
    const float* Wr  = (const float*)d_in[7];
    const float* Wk  = (const float*)d_in[8];
    const float* Wv  = (const float*)d_in[9];
    const float* Wg  = (const float*)d_in[10];
    const float* Wo  = (const float*)d_in[11];
    const float* lnw = (const float*)d_in[12];
    const float* lnb = (const float*)d_in[13];
    float* out = (float*)d_out;

    unsigned char* sc = nullptr;
    cudaGetSymbolAddress((void**)&sc, g_scratch);

    // activation order matches GEMM batch z: r, k, v, g (hi/lo pairs)
    __nv_bfloat16* actb = (__nv_bfloat16*)sc;
    __nv_bfloat16* act[8];
    for (int i = 0; i < 8; i++) act[i] = actb + (size_t)i * ACT_E;
    __nv_bfloat16* wtbase = (__nv_bfloat16*)(sc + 8 * ACT_BB);
    __nv_bfloat16* wt[10];   // wr, wk, wv, wg, wo (hi/lo pairs)
    for (int i = 0; i < 10; i++) wt[i] = wtbase + (size_t)i * W_E;
    float* f32b = (float*)(sc + 8 * ACT_BB + 10 * W_BB);   // r,k,v,g outputs
    float* rb = f32b + 0 * ACT_E;
    float* kb = f32b + 1 * ACT_E;
    float* vb = f32b + 2 * ACT_E;
    float* gb = f32b + 3 * ACT_E;
    float* yb = (float*)act[0];          // aliases xr hi+lo (dead after GEMMs)
    __nv_bfloat16* zh = act[2];          // aliases xk_hi (dead after GEMMs)
    __nv_bfloat16* zl = act[3];          // aliases xk_lo (contiguous pair)

    cudaFuncSetAttribute(gemm_bf16x3, cudaFuncAttributeMaxDynamicSharedMemorySize, GEMM_SMEM);

    // launch 1: fused weight split (order r,k,v,g,o)
    dim3 wgrid(64, 64, 5);
    dim3 wblk(32, 8);
    wsplit_all_kernel<<<wgrid, wblk>>>(Wr, Wk, Wv, Wg, Wo, wtbase);

    // launch 2: mixing (act order: r, k, v, g)
    mix_split_kernel<<<32768, 256>>>(x, tmk, tmv, tmr, tmg,
                                     act[2], act[3], act[4], act[5],
                                     act[0], act[1], act[6], act[7]);

    // launch 3: batched r/k/v/g GEMMs (z=3 gets silu epilogue)
    dim3 ggrid(C_ / BN, M_ / BM, 4);   // (8, 128, 4)
    gemm_bf16x3<<<ggrid, 256, GEMM_SMEM>>>(actb, wtbase, f32b, 3);

    // launch 4: wkv (4-way state split, 256 threads per head)
    wkv_kernel<<<256, 256>>>(rb, kb, vb, dec, faa, yb);

    // launch 5: groupnorm * gate -> bf16 split
    gnorm_kernel<<<65536, 256>>>(yb, gb, lnw, lnb, zh, zl);

    // launch 6: Wo GEMM
    dim3 ogrid(C_ / BN, M_ / BM, 1);
    gemm_bf16x3<<<ogrid, 256, GEMM_SMEM>>>(zh, wt[8], out, -1);
}

// round 14
// speedup vs baseline: 1.3885x; 1.0557x over previous
#include <cuda_runtime.h>
#include <cuda_bf16.h>
#include <math.h>
#include <stdint.h>

#define B_  8
#define T_  2048
#define C_  2048
#define HS_ 64
#define H_  32
#define M_  (B_*T_)   // 16384

// ---------------------------------------------------------------------------
// Static scratch
// ---------------------------------------------------------------------------
#define ACT_E   ((size_t)M_ * C_)          // 33,554,432 elems
#define ACT_BB  (ACT_E * 2)                // 64 MiB per bf16 act buffer
#define W_E     ((size_t)C_ * C_)
#define W_BB    (W_E * 2)                  // 8 MiB per bf16 weight buffer
#define F32_B   (ACT_E * 4)                // 128 MiB per fp32 buffer

__device__ __align__(256) unsigned char g_scratch[8 * ACT_BB + 10 * W_BB + 4 * F32_B];

// ---------------------------------------------------------------------------
// PTX helpers (plain sm_80 PTX — valid under compute_103)
// ---------------------------------------------------------------------------
__device__ __forceinline__ uint32_t smem_u32(const void* p) {
    uint32_t a;
    asm("{ .reg .u64 t; cvta.to.shared.u64 t, %1; cvt.u32.u64 %0, t; }" : "=r"(a) : "l"(p));
    return a;
}

__device__ __forceinline__ void cp16(uint32_t so, const void* gp) {
    asm volatile("cp.async.cg.shared.global [%0], [%1], 16;" :: "r"(so), "l"(gp));
}
#define CP_COMMIT() asm volatile("cp.async.commit_group;" ::: "memory")
#define CP_WAIT2()  asm volatile("cp.async.wait_group 2;" ::: "memory")
#define CP_WAIT0()  asm volatile("cp.async.wait_group 0;" ::: "memory")

__device__ __forceinline__ void ldsm4(uint32_t& r0, uint32_t& r1, uint32_t& r2, uint32_t& r3,
                                      uint32_t addr) {
    asm volatile("ldmatrix.sync.aligned.m8n8.x4.shared.b16 {%0,%1,%2,%3}, [%4];"
                 : "=r"(r0), "=r"(r1), "=r"(r2), "=r"(r3) : "r"(addr));
}

__device__ __forceinline__ void mma16816(float* c, const uint32_t* a, const uint32_t* b) {
    asm("mma.sync.aligned.m16n8k16.row.col.f32.bf16.bf16.f32 "
        "{%0,%1,%2,%3}, {%4,%5,%6,%7}, {%8,%9}, {%0,%1,%2,%3};"
        : "+f"(c[0]), "+f"(c[1]), "+f"(c[2]), "+f"(c[3])
        : "r"(a[0]), "r"(a[1]), "r"(a[2]), "r"(a[3]), "r"(b[0]), "r"(b[1]));
}

// ---------------------------------------------------------------------------
// Fused weight transpose + split (all 5 weights, blockIdx.z selects).
// ---------------------------------------------------------------------------
__global__ __launch_bounds__(256) void wsplit_all_kernel(
    const float* __restrict__ W0, const float* __restrict__ W1,
    const float* __restrict__ W2, const float* __restrict__ W3,
    const float* __restrict__ W4,
    __nv_bfloat16* __restrict__ wtbase)
{
    __shared__ float tile[32][33];
    const float* Ws[5] = {W0, W1, W2, W3, W4};
    const float* W = Ws[blockIdx.z];
    __nv_bfloat16* hi = wtbase + (size_t)(2 * blockIdx.z)     * W_E;
    __nv_bfloat16* lo = wtbase + (size_t)(2 * blockIdx.z + 1) * W_E;

    int tx = threadIdx.x, ty = threadIdx.y;
    int n0 = blockIdx.x * 32, k0 = blockIdx.y * 32;
#pragma unroll
    for (int r = ty; r < 32; r += 8)
        tile[r][tx] = W[(size_t)(k0 + r) * C_ + n0 + tx];
    __syncthreads();
#pragma unroll
    for (int r = ty; r < 32; r += 8) {
        float v = tile[tx][r];                 // = W[k0+tx][n0+r]
        __nv_bfloat16 h = __float2bfloat16(v);
        size_t o = (size_t)(n0 + r) * C_ + k0 + tx;
        hi[o] = h;
        lo[o] = __float2bfloat16(v - __bfloat162float(h));
    }
}

// ---------------------------------------------------------------------------
// Token-shift mixing fused with fp32 -> (bf16 hi, bf16 lo) split.
// ---------------------------------------------------------------------------
__device__ __forceinline__ void split_store4(__nv_bfloat16* hi, __nv_bfloat16* lo,
                                             size_t idx, float4 o) {
    __nv_bfloat16 h0 = __float2bfloat16(o.x);
    __nv_bfloat16 h1 = __float2bfloat16(o.y);
    __nv_bfloat16 h2 = __float2bfloat16(o.z);
    __nv_bfloat16 h3 = __float2bfloat16(o.w);
    __nv_bfloat162* hp = (__nv_bfloat162*)(hi + idx);
    hp[0] = __nv_bfloat162(h0, h1);
    hp[1] = __nv_bfloat162(h2, h3);
    __nv_bfloat162* lp = (__nv_bfloat162*)(lo + idx);
    lp[0] = __nv_bfloat162(__float2bfloat16(o.x - __bfloat162float(h0)),
                           __float2bfloat16(o.y - __bfloat162float(h1)));
    lp[1] = __nv_bfloat162(__float2bfloat16(o.z - __bfloat162float(h2)),
                           __float2bfloat16(o.w - __bfloat162float(h3)));
}

__global__ __launch_bounds__(256) void mix_split_kernel(
    const float* __restrict__ x,
    const float* __restrict__ tmk, const float* __restrict__ tmv,
    const float* __restrict__ tmr, const float* __restrict__ tmg,
    __nv_bfloat16* __restrict__ xkh, __nv_bfloat16* __restrict__ xkl,
    __nv_bfloat16* __restrict__ xvh, __nv_bfloat16* __restrict__ xvl,
    __nv_bfloat16* __restrict__ xrh, __nv_bfloat16* __restrict__ xrl,
    __nv_bfloat16* __restrict__ xgh, __nv_bfloat16* __restrict__ xgl)
{
    size_t idx4 = (size_t)blockIdx.x * blockDim.x + threadIdx.x;
    size_t idx  = idx4 * 4;
    int    c    = (int)(idx % C_);
    size_t m    = idx / C_;
    int    t    = (int)(m % T_);

    float4 xc = *(const float4*)(x + idx);
    float4 xp = make_float4(0.f, 0.f, 0.f, 0.f);
    if (t != 0) xp = *(const float4*)(x + idx - C_);

    float4 o;
#define DO_MIX(TM, HI, LO)                                                  \
    {                                                                       \
        float4 w4 = *(const float4*)((TM) + c);                             \
        o.x = fmaf(w4.x, xc.x - xp.x, xp.x);                                \
        o.y = fmaf(w4.y, xc.y - xp.y, xp.y);                                \
        o.z = fmaf(w4.z, xc.z - xp.z, xp.z);                                \
        o.w = fmaf(w4.w, xc.w - xp.w, xp.w);                                \
        split_store4(HI, LO, idx, o);                                       \
    }
    DO_MIX(tmk, xkh, xkl)
    DO_MIX(tmv, xvh, xvl)
    DO_MIX(tmr, xrh, xrl)
    DO_MIX(tmg, xgh, xgl)
#undef DO_MIX
}

// ---------------------------------------------------------------------------
// bf16x3 GEMM, batched over blockIdx.z (unchanged from R12 WIN config):
// CTA tile 128x256, warp tile 64x64 (8 warps, 256 thr), BK=32, 3 stages.
// ---------------------------------------------------------------------------
#define BM 128
#define BN 256
#define BK 32
#define NCHUNK (2048 / BK)            // 64
#define ROWB 80u                      // 32 bf16 = 64B data, padded to 80B
#define MATA_BYTES (128u * ROWB)      // 10240
#define MATB_BYTES (256u * ROWB)      // 20480
#define STAGE_BYTES (2u * MATA_BYTES + 2u * MATB_BYTES)   // 61440
#define NSTAGE 3
#define GEMM_SMEM (NSTAGE * STAGE_BYTES)   // 184320
#define OFF_AH 0u
#define OFF_AL MATA_BYTES
#define OFF_BH (2u * MATA_BYTES)
#define OFF_BL (2u * MATA_BYTES + MATB_BYTES)

__device__ __forceinline__ void load_stage(
    uint32_t sstage, int k0, int tid, int m0, int n0,
    const __nv_bfloat16* Ah, const __nv_bfloat16* Al,
    const __nv_bfloat16* Bh, const __nv_bfloat16* Bl)
{
#pragma unroll
    for (int j = 0; j < 12; j++) {
        int id = tid + 256 * j;         // 0..3071
        const __nv_bfloat16* base;
        uint32_t roff;
        int cc, grow0;
        if (id < 512)        { cc = id;        base = Ah; roff = OFF_AH; grow0 = m0; }
        else if (id < 1024)  { cc = id - 512;  base = Al; roff = OFF_AL; grow0 = m0; }
        else if (id < 2048)  { cc = id - 1024; base = Bh; roff = OFF_BH; grow0 = n0; }
        else                 { cc = id - 2048; base = Bl; roff = OFF_BL; grow0 = n0; }
        int row = cc >> 2, ch = cc & 3;
        const void* gp = base + (size_t)(grow0 + row) * 2048 + k0 + ch * 8;
        uint32_t so = sstage + roff + (uint32_t)row * ROWB + (uint32_t)ch * 16u;
        cp16(so, gp);
    }
    CP_COMMIT();
}

__global__ __launch_bounds__(256, 1) void gemm_bf16x3(
    const __nv_bfloat16* __restrict__ actb,
    const __nv_bfloat16* __restrict__ wtb,
    float* __restrict__ outb, int epi_z)
{
    extern __shared__ __align__(128) unsigned char dsm[];
    const uint32_t sb = smem_u32(dsm);

    const int z = blockIdx.z;
    const __nv_bfloat16* Ah = actb + (size_t)(2 * z) * ACT_E;
    const __nv_bfloat16* Al = Ah + ACT_E;
    const __nv_bfloat16* Bh = wtb + (size_t)(2 * z) * W_E;
    const __nv_bfloat16* Bl = Bh + W_E;
    float* Cm = outb + (size_t)z * ACT_E;
    const int epi = (z == epi_z);

    const int tid  = threadIdx.x;
    const int wid  = tid >> 5;
    const int lane = tid & 31;
    const int wm   = wid >> 2;          // 0..1 -> warp M origin wm*64
    const int wn   = wid & 3;           // 0..3 -> warp N origin wn*64
    const int m0   = blockIdx.y * BM;
    const int n0   = blockIdx.x * BN;

    float acc[4][8][4];
#pragma unroll
    for (int i = 0; i < 4; i++)
#pragma unroll
        for (int j = 0; j < 8; j++)
#pragma unroll
            for (int q = 0; q < 4; q++) acc[i][j][q] = 0.f;

    const int a_r  = (lane & 15);
    const int a_kb = (lane >> 4) * 16;
    const int b_r  = (lane & 7) + ((lane >> 4) * 8);
    const int b_kb = ((lane >> 3) & 1) * 16;

    // prologue: fill all 3 stages
    load_stage(sb + 0 * STAGE_BYTES, 0 * BK, tid, m0, n0, Ah, Al, Bh, Bl);
    load_stage(sb + 1 * STAGE_BYTES, 1 * BK, tid, m0, n0, Ah, Al, Bh, Bl);
    load_stage(sb + 2 * STAGE_BYTES, 2 * BK, tid, m0, n0, Ah, Al, Bh, Bl);

    for (int i = 0; i < NCHUNK; i++) {
        const uint32_t st = sb + (uint32_t)(i % 3) * STAGE_BYTES;
        CP_WAIT2();               // stage i complete (i+1, i+2 may be pending)
        __syncthreads();

        uint32_t ah[4][4], al[4][4], bh[8][2], bl[8][2];

        // ---- ks = 0 : load frags, compute ----
#pragma unroll
        for (int mi = 0; mi < 4; mi++) {
            uint32_t ao = (uint32_t)(wm * 64 + mi * 16 + a_r) * ROWB + (uint32_t)a_kb;
            ldsm4(ah[mi][0], ah[mi][1], ah[mi][2], ah[mi][3], st + OFF_AH + ao);
            ldsm4(al[mi][0], al[mi][1], al[mi][2], al[mi][3], st + OFF_AL + ao);
        }
#pragma unroll
        for (int bi = 0; bi < 4; bi++) {
            uint32_t bo = (uint32_t)(wn * 64 + bi * 16 + b_r) * ROWB + (uint32_t)b_kb;
            uint32_t t0, t1, t2, t3;
            ldsm4(t0, t1, t2, t3, st + OFF_BH + bo);
            bh[bi * 2][0] = t0; bh[bi * 2][1] = t1;
            bh[bi * 2 + 1][0] = t2; bh[bi * 2 + 1][1] = t3;
            ldsm4(t0, t1, t2, t3, st + OFF_BL + bo);
            bl[bi * 2][0] = t0; bl[bi * 2][1] = t1;
            bl[bi * 2 + 1][0] = t2; bl[bi * 2 + 1][1] = t3;
        }
#pragma unroll
        for (int mi = 0; mi < 4; mi++)
#pragma unroll
            for (int ng = 0; ng < 8; ng++) {
                mma16816(acc[mi][ng], ah[mi], bh[ng]);
                mma16816(acc[mi][ng], ah[mi], bl[ng]);
                mma16816(acc[mi][ng], al[mi], bh[ng]);
            }

        // ---- ks = 1 : load frags, release stage, refill, compute ----
#pragma unroll
        for (int mi = 0; mi < 4; mi++) {
            uint32_t ao = (uint32_t)(wm * 64 + mi * 16 + a_r) * ROWB + (uint32_t)(32 + a_kb);
            ldsm4(ah[mi][0], ah[mi][1], ah[mi][2], ah[mi][3], st + OFF_AH + ao);
            ldsm4(al[mi][0], al[mi][1], al[mi][2], al[mi][3], st + OFF_AL + ao);
        }
#pragma unroll
        for (int bi = 0; bi < 4; bi++) {
            uint32_t bo = (uint32_t)(wn * 64 + bi * 16 + b_r) * ROWB + (uint32_t)(32 + b_kb);
            uint32_t t0, t1, t2, t3;
            ldsm4(t0, t1, t2, t3, st + OFF_BH + bo);
            bh[bi * 2][0] = t0; bh[bi * 2][1] = t1;
            bh[bi * 2 + 1][0] = t2; bh[bi * 2 + 1][1] = t3;
            ldsm4(t0, t1, t2, t3, st + OFF_BL + bo);
            bl[bi * 2][0] = t0; bl[bi * 2][1] = t1;
            bl[bi * 2 + 1][0] = t2; bl[bi * 2 + 1][1] = t3;
        }
        __syncthreads();          // all warps done reading stage i
        if (i + 3 < NCHUNK)
            load_stage(st, (i + 3) * BK, tid, m0, n0, Ah, Al, Bh, Bl);
        else
            CP_COMMIT();          // keep wait_group accounting uniform
#pragma unroll
        for (int mi = 0; mi < 4; mi++)
#pragma unroll
            for (int ng = 0; ng < 8; ng++) {
                mma16816(acc[mi][ng], ah[mi], bh[ng]);
                mma16816(acc[mi][ng], ah[mi], bl[ng]);
                mma16816(acc[mi][ng], al[mi], bh[ng]);
            }
    }
    CP_WAIT0();

    // epilogue
#pragma unroll
    for (int mi = 0; mi < 4; mi++) {
        int row0 = m0 + wm * 64 + mi * 16 + (lane >> 2);
#pragma unroll
        for (int ng = 0; ng < 8; ng++) {
            int col = n0 + wn * 64 + ng * 8 + (lane & 3) * 2;
            float2 v0 = make_float2(acc[mi][ng][0], acc[mi][ng][1]);
            float2 v1 = make_float2(acc[mi][ng][2], acc[mi][ng][3]);
            if (epi) {
                v0.x = v0.x / (1.f + expf(-v0.x));
                v0.y = v0.y / (1.f + expf(-v0.y));
                v1.x = v1.x / (1.f + expf(-v1.x));
                v1.y = v1.y / (1.f + expf(-v1.y));
            }
            *(float2*)(Cm + (size_t)row0 * 2048 + col)       = v0;
            *(float2*)(Cm + (size_t)(row0 + 8) * 2048 + col) = v1;
        }
    }
}

// ---------------------------------------------------------------------------
// WKV5 recurrence, 4-way state split + cp.async double buffering.
// 256 threads per (b,h): thread (j,q) owns S[i][j], i in [q*16, q*16+16).
// Per chunk: prefetch next chunk overlaps compute; all quarters write y
// partials; quarter q reduces + stores timesteps [4q, 4q+4).
// ---------------------------------------------------------------------------
#define CH 16
__global__ __launch_bounds__(256) void wkv_kernel(
    const float* __restrict__ r, const float* __restrict__ k,
    const float* __restrict__ v, const float* __restrict__ decay,
    const float* __restrict__ faaaa, float* __restrict__ y)
{
    const int bh  = blockIdx.x;
    const int b   = bh / H_;
    const int h   = bh % H_;
    const int tid = threadIdx.x;
    const int j   = tid & 63;
    const int q   = tid >> 6;           // 0..3
    const int i0  = q * 16;

    __shared__ float rs[2][CH][HS_], ks_[2][CH][HS_], vs[2][CH][HS_];
    __shared__ float part[4][CH][HS_];
    __shared__ float cpart[4][CH];
    __shared__ float ws[HS_], us[HS_];

    if (q == 0) {
        ws[j] = expf(-expf(decay[h * HS_ + j]));
        us[j] = faaaa[h * HS_ + j];
    }

    float S[16];
#pragma unroll
    for (int i = 0; i < 16; i++) S[i] = 0.f;

    const size_t base = (size_t)b * T_ * C_ + h * HS_;

    // prefetch addressing: thread loads one float4 per array per chunk
    const int prow = tid >> 4;          // 0..15 (timestep within chunk)
    const int pc4  = (tid & 15) * 4;    // 0..60 (column, float4 aligned)

#define WKV_PREFETCH(BUF, T0)                                                 \
    {                                                                         \
        size_t goff = base + (size_t)((T0) + prow) * C_ + pc4;                \
        cp16(smem_u32(&rs[BUF][prow][pc4]),  r + goff);                       \
        cp16(smem_u32(&ks_[BUF][prow][pc4]), k + goff);                       \
        cp16(smem_u32(&vs[BUF][prow][pc4]),  v + goff);                       \
        CP_COMMIT();                                                          \
    }

    WKV_PREFETCH(0, 0)

    for (int t0 = 0; t0 < T_; t0 += CH) {
        const int buf = (t0 >> 4) & 1;
        CP_WAIT0();                 // chunk t0's data landed
        __syncthreads();            // everyone past previous chunk's smem reads
        if (t0 + CH < T_) WKV_PREFETCH(buf ^ 1, t0 + CH)   // overlaps compute

        // per-quarter partial of c_t = sum_i r_i*u_i*k_i  (16 threads/quarter)
        if (j < CH) {
            float c = 0.f;
#pragma unroll
            for (int i = 0; i < 16; i++)
                c = fmaf(rs[buf][j][i0 + i] * us[i0 + i], ks_[buf][j][i0 + i], c);
            cpart[q][j] = c;
        }

        // recurrence over 16 timesteps; 4 accumulators break the dep chain
        float yy[CH];
        for (int s = 0; s < CH; s++) {
            float vj = vs[buf][s][j];
            float a0 = 0.f, a1 = 0.f, a2 = 0.f, a3 = 0.f;
#pragma unroll
            for (int i = 0; i < 16; i += 4) {
                a0 = fmaf(rs[buf][s][i0 + i],     S[i],     a0);
                a1 = fmaf(rs[buf][s][i0 + i + 1], S[i + 1], a1);
                a2 = fmaf(rs[buf][s][i0 + i + 2], S[i + 2], a2);
                a3 = fmaf(rs[buf][s][i0 + i + 3], S[i + 3], a3);
                S[i]     = fmaf(ws[i0 + i],     S[i],     ks_[buf][s][i0 + i]     * vj);
                S[i + 1] = fmaf(ws[i0 + i + 1], S[i + 1], ks_[buf][s][i0 + i + 1] * vj);
                S[i + 2] = fmaf(ws[i0 + i + 2], S[i + 2], ks_[buf][s][i0 + i + 2] * vj);
                S[i + 3] = fmaf(ws[i0 + i + 3], S[i + 3], ks_[buf][s][i0 + i + 3] * vj);
            }
            yy[s] = (a0 + a1) + (a2 + a3);
        }
#pragma unroll
        for (int s = 0; s < CH; s++) part[q][s][j] = yy[s];
        __syncthreads();

        // distributed reduce + store: quarter q handles s in [4q, 4q+4)
#pragma unroll
        for (int ss = 0; ss < 4; ss++) {
            int s = q * 4 + ss;
            float c = (cpart[0][s] + cpart[1][s]) + (cpart[2][s] + cpart[3][s]);
            float sum = (part[0][s][j] + part[1][s][j]) + (part[2][s][j] + part[3][s][j]);
            y[base + (size_t)(t0 + s) * C_ + j] = sum + c * vs[buf][s][j];
        }
    }
}
#undef CH

// ---------------------------------------------------------------------------
// GroupNorm (/8, per head) * gate, output split to bf16 hi/lo for Wo GEMM.
// ---------------------------------------------------------------------------
__global__ __launch_bounds__(256) void gnorm_kernel(
    const float* __restrict__ y, const float* __restrict__ g,
    const float* __restrict__ lnw, const float* __restrict__ lnb,
    __nv_bfloat16* __restrict__ zh, __nv_bfloat16* __restrict__ zl)
{
    int warp = blockIdx.x * 8 + (threadIdx.x >> 5);
    int lane = threadIdx.x & 31;
    int row  = warp / H_;
    int h    = warp % H_;

    const size_t o0 = (size_t)row * C_ + h * HS_ + lane;
    float a0 = y[o0]      * 0.125f;
    float a1 = y[o0 + 32] * 0.125f;

    float s = a0 + a1;
#pragma unroll
    for (int o = 16; o; o >>= 1) s += __shfl_xor_sync(0xffffffffu, s, o);
    float mean = s * (1.f / 64.f);

    float d0 = a0 - mean, d1 = a1 - mean;
    float q = d0 * d0 + d1 * d1;
#pragma unroll
    for (int o = 16; o; o >>= 1) q += __shfl_xor_sync(0xffffffffu, q, o);
    float inv = rsqrtf(q * (1.f / 64.f) + 1e-5f);

    int c = h * HS_ + lane;
    float z0 = fmaf(d0 * inv, lnw[c],      lnb[c])      * g[o0];
    float z1 = fmaf(d1 * inv, lnw[c + 32], lnb[c + 32]) * g[o0 + 32];

    __nv_bfloat16 h0 = __float2bfloat16(z0);
    __nv_bfloat16 h1 = __float2bfloat16(z1);
    zh[o0]      = h0;
    zh[o0 + 32] = h1;
    zl[o0]      = __float2bfloat16(z0 - __bfloat162float(h0));
    zl[o0 + 32] = __float2bfloat16(z1 - __bfloat162float(h1));
}

// ---------------------------------------------------------------------------
extern "C" void kernel_launch(void* const* d_in, const int* in_sizes, int n_in,
                              void* d_out, int out_size)
{
    const float* x   = (const float*)d_in[0];
    const float* tmk = (const float*)d_in[1];
    const float* tmv = (const float*)d_in[2];
    const float* tmr = (const float*)d_in[3];
    const float* tmg = (const float*)d_in[4];
    const float* dec = (const float*)d_in[5];
    const float* faa = (const float*)d_in[6];
    const float* Wr  = (const float*)d_in[7];
    const float* Wk  = (const float*)d_in[8];
    const float* Wv  = (const float*)d_in[9];
    const float* Wg  = (const float*)d_in[10];
    const float* Wo  = (const float*)d_in[11];
    const float* lnw = (const float*)d_in[12];
    const float* lnb = (const float*)d_in[13];
    float* out = (float*)d_out;

    unsigned char* sc = nullptr;
    cudaGetSymbolAddress((void**)&sc, g_scratch);

    // activation order matches GEMM batch z: r, k, v, g (hi/lo pairs)
    __nv_bfloat16* actb = (__nv_bfloat16*)sc;
    __nv_bfloat16* act[8];
    for (int i = 0; i < 8; i++) act[i] = actb + (size_t)i * ACT_E;
    __nv_bfloat16* wtbase = (__nv_bfloat16*)(sc + 8 * ACT_BB);
    __nv_bfloat16* wt[10];   // wr, wk, wv, wg, wo (hi/lo pairs)
    for (int i = 0; i < 10; i++) wt[i] = wtbase + (size_t)i * W_E;
    float* f32b = (float*)(sc + 8 * ACT_BB + 10 * W_BB);   // r,k,v,g outputs
    float* rb = f32b + 0 * ACT_E;
    float* kb = f32b + 1 * ACT_E;
    float* vb = f32b + 2 * ACT_E;
    float* gb = f32b + 3 * ACT_E;
    float* yb = (float*)act[0];          // aliases xr hi+lo (dead after GEMMs)
    __nv_bfloat16* zh = act[2];          // aliases xk_hi (dead after GEMMs)
    __nv_bfloat16* zl = act[3];          // aliases xk_lo (contiguous pair)

    cudaFuncSetAttribute(gemm_bf16x3, cudaFuncAttributeMaxDynamicSharedMemorySize, GEMM_SMEM);

    // launch 1: fused weight split (order r,k,v,g,o)
    dim3 wgrid(64, 64, 5);
    dim3 wblk(32, 8);
    wsplit_all_kernel<<<wgrid, wblk>>>(Wr, Wk, Wv, Wg, Wo, wtbase);

    // launch 2: mixing (act order: r, k, v, g)
    mix_split_kernel<<<32768, 256>>>(x, tmk, tmv, tmr, tmg,
                                     act[2], act[3], act[4], act[5],
                                     act[0], act[1], act[6], act[7]);

    // launch 3: batched r/k/v/g GEMMs (z=3 gets silu epilogue)
    dim3 ggrid(C_ / BN, M_ / BM, 4);   // (8, 128, 4)
    gemm_bf16x3<<<ggrid, 256, GEMM_SMEM>>>(actb, wtbase, f32b, 3);

    // launch 4: wkv (4-way state split + double-buffered prefetch)
    wkv_kernel<<<256, 256>>>(rb, kb, vb, dec, faa, yb);

    // launch 5: groupnorm * gate -> bf16 split
    gnorm_kernel<<<65536, 256>>>(yb, gb, lnw, lnb, zh, zl);

    // launch 6: Wo GEMM
    dim3 ogrid(C_ / BN, M_ / BM, 1);
    gemm_bf16x3<<<ogrid, 256, GEMM_SMEM>>>(zh, wt[8], out, -1);
}